// round 1
// baseline (speedup 1.0000x reference)
#include <cuda_runtime.h>
#include <cuda_bf16.h>
#include <cstdint>

// ---------------------------------------------------------------------------
// MambaBlock: out = x + out_proj( gate( selective_scan( conv(in_proj(LN(x))) ) ) )
// B=2, L=1024, D_MODEL=1024, D_INNER=2048, DT_RANK=64, D_STATE=16, D_CONV=4
// Tokens M = B*L = 2048.
// Layout convention for intermediates: channel-major  buf[d][token],
// token = b*1024 + l  (contiguous over l within a batch).
// ---------------------------------------------------------------------------

#define NTOK    2048
#define DMODEL  1024
#define DINNER  2048
#define DSTATE  16
#define DTRANK  64
#define XDBL_N  96          // DT_RANK + 2*D_STATE
#define SPLITK  8

// scratch (static device allocations, ~95 MB)
__device__ float g_h   [NTOK * DMODEL];        // layernorm out, token-major
__device__ float g_xt  [DINNER * NTOK];        // x_in   (channel-major)
__device__ float g_zt  [DINNER * NTOK];        // z      (channel-major)
__device__ float g_xct [DINNER * NTOK];        // silu(conv(x_in))
__device__ float g_dtt [DINNER * NTOK];        // softplus(dt)
__device__ float g_yt  [DINNER * NTOK];        // gated scan output
__device__ float g_xdbl[NTOK * XDBL_N];        // x_proj out, token-major
__device__ float g_xdbl_part[SPLITK * NTOK * XDBL_N];

// ---------------------------------------------------------------------------
// LayerNorm: one block per token, 256 threads, float4 (256*4 = 1024 elems)
// ---------------------------------------------------------------------------
__global__ void __launch_bounds__(256) ln_kernel(
    const float* __restrict__ x, const float* __restrict__ w,
    const float* __restrict__ b, float* __restrict__ out)
{
    const int t = blockIdx.x;
    const float4 v = reinterpret_cast<const float4*>(x + (size_t)t * DMODEL)[threadIdx.x];
    float s  = v.x + v.y + v.z + v.w;
    float sq = v.x*v.x + v.y*v.y + v.z*v.z + v.w*v.w;

    __shared__ float sa[8], sb[8];
    int lane = threadIdx.x & 31, wrp = threadIdx.x >> 5;
    #pragma unroll
    for (int o = 16; o; o >>= 1) {
        s  += __shfl_down_sync(0xffffffffu, s,  o);
        sq += __shfl_down_sync(0xffffffffu, sq, o);
    }
    if (lane == 0) { sa[wrp] = s; sb[wrp] = sq; }
    __syncthreads();
    if (wrp == 0) {
        s  = (lane < 8) ? sa[lane] : 0.f;
        sq = (lane < 8) ? sb[lane] : 0.f;
        #pragma unroll
        for (int o = 4; o; o >>= 1) {
            s  += __shfl_down_sync(0xffffffffu, s,  o);
            sq += __shfl_down_sync(0xffffffffu, sq, o);
        }
        if (lane == 0) { sa[0] = s; sb[0] = sq; }
    }
    __syncthreads();
    const float mu  = sa[0] * (1.f / DMODEL);
    const float var = sb[0] * (1.f / DMODEL) - mu * mu;
    const float inv = rsqrtf(var + 1e-5f);

    const float4 wv = reinterpret_cast<const float4*>(w)[threadIdx.x];
    const float4 bv = reinterpret_cast<const float4*>(b)[threadIdx.x];
    float4 o4;
    o4.x = (v.x - mu) * inv * wv.x + bv.x;
    o4.y = (v.y - mu) * inv * wv.y + bv.y;
    o4.z = (v.z - mu) * inv * wv.z + bv.z;
    o4.w = (v.w - mu) * inv * wv.w + bv.w;
    reinterpret_cast<float4*>(out + (size_t)t * DMODEL)[threadIdx.x] = o4;
}

// ---------------------------------------------------------------------------
// Generic tiled SGEMM: C[m][n] = sum_k A(m,k) * B[n][k]   (B always row-major NxK)
//   ACOL=false : A row-major (M,K), row stride lda
//   ACOL=true  : A stored K-major: A[k*lda + m]  (lda = M)
// MODE 0: C[z*M*N + m*N + n] = acc                (split-K partial slabs)
// MODE 1: n <  N/2 : C [n*M + m]  = acc           (in_proj split → xt)
//         n >= N/2 : C2[(n-N/2)*M + m] = acc      (→ zt)
// MODE 2: C[n*M + m] = softplus(acc + bias[n])    (dt, transposed out)
// MODE 3: C[m*N + n] = acc + resid[m*N + n]       (out_proj + residual)
// ---------------------------------------------------------------------------
#define BM 128
#define BN 64
#define BKT 16

template<int MODE, bool ACOL>
__global__ void __launch_bounds__(256) gemm_k(
    const float* __restrict__ A, int lda, const float* __restrict__ B,
    float* __restrict__ C, float* __restrict__ C2,
    const float* __restrict__ bias, const float* __restrict__ resid,
    int M, int N, int K, int kSplitLen)
{
    __shared__ float As[BKT][BM];
    __shared__ float Bs[BKT][BN];

    const int tid = threadIdx.x;
    const int n0 = blockIdx.x * BN;
    const int m0 = blockIdx.y * BM;
    const int kBase = blockIdx.z * kSplitLen;
    const int kEnd  = kBase + kSplitLen;
    const int tm = tid >> 4, tn = tid & 15;

    float acc[8][4];
    #pragma unroll
    for (int i = 0; i < 8; i++)
        #pragma unroll
        for (int j = 0; j < 4; j++) acc[i][j] = 0.f;

    for (int k0 = kBase; k0 < kEnd; k0 += BKT) {
        if (ACOL) {
            const int m4 = tid & 31, kr = tid >> 5;
            #pragma unroll
            for (int it = 0; it < 2; it++) {
                const int k = kr + it * 8;
                const float4 v = *reinterpret_cast<const float4*>(
                    A + (size_t)(k0 + k) * lda + m0 + m4 * 4);
                *reinterpret_cast<float4*>(&As[k][m4 * 4]) = v;
            }
        } else {
            const int r = tid >> 2, kq = tid & 3;
            #pragma unroll
            for (int it = 0; it < 2; it++) {
                const int m = r + it * 64;
                const float4 v = *reinterpret_cast<const float4*>(
                    A + (size_t)(m0 + m) * lda + k0 + kq * 4);
                As[kq*4+0][m] = v.x; As[kq*4+1][m] = v.y;
                As[kq*4+2][m] = v.z; As[kq*4+3][m] = v.w;
            }
        }
        {
            const int nr = tid >> 2, kq = tid & 3;
            float4 v = make_float4(0.f, 0.f, 0.f, 0.f);
            if (n0 + nr < N)
                v = *reinterpret_cast<const float4*>(
                    B + (size_t)(n0 + nr) * K + k0 + kq * 4);
            Bs[kq*4+0][nr] = v.x; Bs[kq*4+1][nr] = v.y;
            Bs[kq*4+2][nr] = v.z; Bs[kq*4+3][nr] = v.w;
        }
        __syncthreads();

        #pragma unroll
        for (int kk = 0; kk < BKT; kk++) {
            float a[8], bb[4];
            #pragma unroll
            for (int i = 0; i < 8; i++) a[i] = As[kk][tm * 8 + i];
            #pragma unroll
            for (int j = 0; j < 4; j++) bb[j] = Bs[kk][tn * 4 + j];
            #pragma unroll
            for (int i = 0; i < 8; i++)
                #pragma unroll
                for (int j = 0; j < 4; j++)
                    acc[i][j] = fmaf(a[i], bb[j], acc[i][j]);
        }
        __syncthreads();
    }

    const int half = N >> 1;
    #pragma unroll
    for (int i = 0; i < 8; i++) {
        const int m = m0 + tm * 8 + i;
        #pragma unroll
        for (int j = 0; j < 4; j++) {
            const int n = n0 + tn * 4 + j;
            if (n >= N) continue;
            float v = acc[i][j];
            if (MODE == 0) {
                C[(size_t)blockIdx.z * M * N + (size_t)m * N + n] = v;
            } else if (MODE == 1) {
                if (n < half) C [(size_t)n * M + m] = v;
                else          C2[(size_t)(n - half) * M + m] = v;
            } else if (MODE == 2) {
                v += bias[n];
                v = (v > 20.f) ? v : log1pf(expf(v));
                C[(size_t)n * M + m] = v;
            } else {
                C[(size_t)m * N + n] = v + resid[(size_t)m * N + n];
            }
        }
    }
}

// ---------------------------------------------------------------------------
// split-K reduction for x_proj
// ---------------------------------------------------------------------------
__global__ void __launch_bounds__(256) reduce_k(
    const float* __restrict__ part, float* __restrict__ out, int n)
{
    const int i = blockIdx.x * 256 + threadIdx.x;
    if (i < n) {
        float s = 0.f;
        #pragma unroll
        for (int z = 0; z < SPLITK; z++) s += part[(size_t)z * n + i];
        out[i] = s;
    }
}

// ---------------------------------------------------------------------------
// Depthwise causal conv1d (d_conv=4) + silu. One block per (d, b) row.
// ---------------------------------------------------------------------------
__global__ void __launch_bounds__(256) conv_kernel(
    const float* __restrict__ xt, const float* __restrict__ cw,
    const float* __restrict__ cb, float* __restrict__ xct)
{
    const int row = blockIdx.x;          // 0..4095
    const int d = row >> 1, b = row & 1;
    const size_t base = (size_t)d * NTOK + b * 1024;

    __shared__ float s[1024 + 3];
    const int tid = threadIdx.x;
    const float4 v = reinterpret_cast<const float4*>(xt + base)[tid];
    s[3 + tid*4 + 0] = v.x; s[3 + tid*4 + 1] = v.y;
    s[3 + tid*4 + 2] = v.z; s[3 + tid*4 + 3] = v.w;
    if (tid == 0) { s[0] = 0.f; s[1] = 0.f; s[2] = 0.f; }
    __syncthreads();

    const float w0 = cw[d*4+0], w1 = cw[d*4+1], w2 = cw[d*4+2], w3 = cw[d*4+3];
    const float bs = cb[d];
    float4 o;
    #pragma unroll
    for (int i = 0; i < 4; i++) {
        const int l = tid * 4 + i;
        float r = bs + w0*s[l] + w1*s[l+1] + w2*s[l+2] + w3*s[l+3];
        r = r / (1.f + __expf(-r));     // silu
        ((float*)&o)[i] = r;
    }
    reinterpret_cast<float4*>(xct + base)[tid] = o;
}

// ---------------------------------------------------------------------------
// Selective scan. 16 lanes per (b,d) chain, one lane per state s.
//   h_t = exp(dt*A[d,s]) * h_{t-1} + dt * B_t[s] * xc_t
//   y_t = (sum_s h_t[s]*C_t[s] + xc_t*D[d]) * silu(z_t)
// ---------------------------------------------------------------------------
__global__ void __launch_bounds__(256) scan_kernel(
    const float* __restrict__ xdbl, const float* __restrict__ dtt,
    const float* __restrict__ xct,  const float* __restrict__ zt,
    const float* __restrict__ A_log, const float* __restrict__ Dp,
    float* __restrict__ yt)
{
    const int gt = blockIdx.x * blockDim.x + threadIdx.x;
    const int g = gt >> 4, s = gt & 15;
    const int b = g >> 11, d = g & 2047;       // g = b*2048 + d

    const float Ac = -expf(A_log[d * DSTATE + s]);
    const float Dd = Dp[d];
    const size_t base = (size_t)d * NTOK + b * 1024;
    const float* __restrict__ dtp = dtt + base;
    const float* __restrict__ xcp = xct + base;
    const float* __restrict__ zp  = zt  + base;
    float*       __restrict__ yp  = yt  + base;
    const float* __restrict__ xd  = xdbl + (size_t)(b * 1024) * XDBL_N;

    float h = 0.f;
    for (int t = 0; t < 1024; t++) {
        const float dt = dtp[t];
        const float xc = xcp[t];
        const float bsv = xd[t * XDBL_N + DTRANK + s];
        const float csv = xd[t * XDBL_N + DTRANK + DSTATE + s];
        const float da = __expf(dt * Ac);
        h = fmaf(da, h, dt * bsv * xc);
        float p = h * csv;
        p += __shfl_xor_sync(0xffffffffu, p, 8, 16);
        p += __shfl_xor_sync(0xffffffffu, p, 4, 16);
        p += __shfl_xor_sync(0xffffffffu, p, 2, 16);
        p += __shfl_xor_sync(0xffffffffu, p, 1, 16);
        if (s == 0) {
            const float zv = zp[t];
            const float gate = zv / (1.f + __expf(-zv));
            yp[t] = (p + xc * Dd) * gate;
        }
    }
}

// ---------------------------------------------------------------------------
// host
// ---------------------------------------------------------------------------
extern "C" void kernel_launch(void* const* d_in, const int* in_sizes, int n_in,
                              void* d_out, int out_size)
{
    const float* x        = (const float*)d_in[0];
    const float* ln_w     = (const float*)d_in[1];
    const float* ln_b     = (const float*)d_in[2];
    const float* in_w     = (const float*)d_in[3];   // (4096, 1024)
    const float* conv_w   = (const float*)d_in[4];   // (2048, 1, 4)
    const float* conv_b   = (const float*)d_in[5];
    const float* xproj_w  = (const float*)d_in[6];   // (96, 2048)
    const float* dtproj_w = (const float*)d_in[7];   // (2048, 64)
    const float* dtproj_b = (const float*)d_in[8];
    const float* A_log    = (const float*)d_in[9];   // (2048, 16)
    const float* Dp       = (const float*)d_in[10];  // (2048,)
    const float* out_w    = (const float*)d_in[11];  // (1024, 2048)
    float* out = (float*)d_out;

    float *h, *xt, *zt, *xct, *dtt, *yt, *xdbl, *xdblp;
    cudaGetSymbolAddress((void**)&h,     g_h);
    cudaGetSymbolAddress((void**)&xt,    g_xt);
    cudaGetSymbolAddress((void**)&zt,    g_zt);
    cudaGetSymbolAddress((void**)&xct,   g_xct);
    cudaGetSymbolAddress((void**)&dtt,   g_dtt);
    cudaGetSymbolAddress((void**)&yt,    g_yt);
    cudaGetSymbolAddress((void**)&xdbl,  g_xdbl);
    cudaGetSymbolAddress((void**)&xdblp, g_xdbl_part);

    // 1. layernorm
    ln_kernel<<<NTOK, 256>>>(x, ln_w, ln_b, h);

    // 2. in_proj: (2048 x 1024) @ (4096 x 1024)^T, split-write transposed xt/zt
    gemm_k<1, false><<<dim3(4096 / BN, NTOK / BM, 1), 256>>>(
        h, DMODEL, in_w, xt, zt, nullptr, nullptr, NTOK, 2 * DINNER, DMODEL, DMODEL);

    // 3. depthwise conv + silu
    conv_kernel<<<DINNER * 2, 256>>>(xt, conv_w, conv_b, xct);

    // 4. x_proj: (2048 x 2048[K-major]) @ (96 x 2048)^T, split-K=8
    gemm_k<0, true><<<dim3(2, NTOK / BM, SPLITK), 256>>>(
        xct, NTOK, xproj_w, xdblp, nullptr, nullptr, nullptr,
        NTOK, XDBL_N, DINNER, DINNER / SPLITK);
    reduce_k<<<(NTOK * XDBL_N + 255) / 256, 256>>>(xdblp, xdbl, NTOK * XDBL_N);

    // 5. dt = softplus(xdbl[:, :64] @ dt_proj_w^T + b), transposed out
    gemm_k<2, false><<<dim3(DINNER / BN, NTOK / BM, 1), 256>>>(
        xdbl, XDBL_N, dtproj_w, dtt, nullptr, dtproj_b, nullptr,
        NTOK, DINNER, DTRANK, DTRANK);

    // 6. selective scan + D skip + silu(z) gating
    scan_kernel<<<(2 * DINNER * DSTATE) / 256, 256>>>(
        xdbl, dtt, xct, zt, A_log, Dp, yt);

    // 7. out_proj + residual
    gemm_k<3, true><<<dim3(DMODEL / BN, NTOK / BM, 1), 256>>>(
        yt, NTOK, out_w, out, nullptr, nullptr, x,
        NTOK, DMODEL, DINNER, DINNER);
}

// round 4
// speedup vs baseline: 1.0129x; 1.0129x over previous
#include <cuda_runtime.h>
#include <cuda_bf16.h>
#include <cstdint>

// ---------------------------------------------------------------------------
// MambaBlock: out = x + out_proj( gate( selective_scan( conv(in_proj(LN(x))) ) ) )
// B=2, L=1024, D_MODEL=1024, D_INNER=2048, DT_RANK=64, D_STATE=16, D_CONV=4
// Intermediates channel-major: buf[d][token], token = b*1024 + l.
// GEMMs use packed fma.rn.f32x2 (2x fp32) + double-buffered SMEM.
// ---------------------------------------------------------------------------

#define NTOK    2048
#define DMODEL  1024
#define DINNER  2048
#define DSTATE  16
#define DTRANK  64
#define XDBL_N  96
#define SPLITK  8

__device__ float g_h   [NTOK * DMODEL];
__device__ float g_xt  [DINNER * NTOK];
__device__ float g_zt  [DINNER * NTOK];
__device__ float g_xct [DINNER * NTOK];
__device__ float g_dtt [DINNER * NTOK];
__device__ float g_yt  [DINNER * NTOK];
__device__ float g_xdbl[NTOK * XDBL_N];
__device__ float g_xdbl_part[SPLITK * NTOK * XDBL_N];

// ---------------------------------------------------------------------------
// packed-fp32 helpers
// ---------------------------------------------------------------------------
__device__ __forceinline__ unsigned long long dup2(float x) {
    unsigned long long r;
    asm("mov.b64 %0, {%1, %1};" : "=l"(r) : "f"(x));
    return r;
}
__device__ __forceinline__ void fma2(unsigned long long& d,
                                     unsigned long long a,
                                     unsigned long long b) {
    asm("fma.rn.f32x2 %0, %1, %2, %0;" : "+l"(d) : "l"(a), "l"(b));
}

// ---------------------------------------------------------------------------
// LayerNorm
// ---------------------------------------------------------------------------
__global__ void __launch_bounds__(256) ln_kernel(
    const float* __restrict__ x, const float* __restrict__ w,
    const float* __restrict__ b, float* __restrict__ out)
{
    const int t = blockIdx.x;
    const float4 v = reinterpret_cast<const float4*>(x + (size_t)t * DMODEL)[threadIdx.x];
    float s  = v.x + v.y + v.z + v.w;
    float sq = v.x*v.x + v.y*v.y + v.z*v.z + v.w*v.w;

    __shared__ float sa[8], sb[8];
    int lane = threadIdx.x & 31, wrp = threadIdx.x >> 5;
    #pragma unroll
    for (int o = 16; o; o >>= 1) {
        s  += __shfl_down_sync(0xffffffffu, s,  o);
        sq += __shfl_down_sync(0xffffffffu, sq, o);
    }
    if (lane == 0) { sa[wrp] = s; sb[wrp] = sq; }
    __syncthreads();
    if (wrp == 0) {
        s  = (lane < 8) ? sa[lane] : 0.f;
        sq = (lane < 8) ? sb[lane] : 0.f;
        #pragma unroll
        for (int o = 4; o; o >>= 1) {
            s  += __shfl_down_sync(0xffffffffu, s,  o);
            sq += __shfl_down_sync(0xffffffffu, sq, o);
        }
        if (lane == 0) { sa[0] = s; sb[0] = sq; }
    }
    __syncthreads();
    const float mu  = sa[0] * (1.f / DMODEL);
    const float var = sb[0] * (1.f / DMODEL) - mu * mu;
    const float inv = rsqrtf(var + 1e-5f);

    const float4 wv = reinterpret_cast<const float4*>(w)[threadIdx.x];
    const float4 bv = reinterpret_cast<const float4*>(b)[threadIdx.x];
    float4 o4;
    o4.x = (v.x - mu) * inv * wv.x + bv.x;
    o4.y = (v.y - mu) * inv * wv.y + bv.y;
    o4.z = (v.z - mu) * inv * wv.z + bv.z;
    o4.w = (v.w - mu) * inv * wv.w + bv.w;
    reinterpret_cast<float4*>(out + (size_t)t * DMODEL)[threadIdx.x] = o4;
}

// ---------------------------------------------------------------------------
// Tiled SGEMM, fma.rn.f32x2, double-buffered.
//   C[m][n] = sum_k A(m,k) * B[n][k]   (B row-major N x K)
//   ACOL=false: A row-major (lda=K-ish row stride). ACOL=true: A[k*lda + m].
// MODE 0: split-K partial slabs  C[z*M*N + m*N + n]
// MODE 1: n<N/2 -> C[n*M+m] ; else C2[(n-N/2)*M+m]    (in_proj -> xt/zt)
// MODE 2: C[n*M+m] = softplus(acc + bias[n])          (dt)
// MODE 3: C[m*N+n] = acc + resid[m*N+n]               (out_proj + residual)
// Microtile: 8(m) x TN(n) per thread; BM=128, BN=16*TN, 256 threads.
// ---------------------------------------------------------------------------
#define BM  128
#define BKT 16
#define APAD 4

template<int MODE, bool ACOL, int TN>
__global__ void __launch_bounds__(256) gemm_k(
    const float* __restrict__ A, int lda, const float* __restrict__ B,
    float* __restrict__ C, float* __restrict__ C2,
    const float* __restrict__ bias, const float* __restrict__ resid,
    int M, int N, int K, int kSplitLen)
{
    constexpr int BN = TN * 16;
    __shared__ __align__(16) float As[2][BKT][BM + APAD];
    __shared__ __align__(16) float Bs[2][BKT][BN];

    const int tid = threadIdx.x;
    const int n0 = blockIdx.x * BN;
    const int m0 = blockIdx.y * BM;
    const int kBase = blockIdx.z * kSplitLen;
    const int nT = kSplitLen / BKT;
    const int tm = tid >> 4, tn = tid & 15;

    unsigned long long acc[TN][4];
    #pragma unroll
    for (int j = 0; j < TN; j++)
        #pragma unroll
        for (int p = 0; p < 4; p++) acc[j][p] = 0ull;

    float4 ar0, ar1, br0, br1;

#define LOAD_A(k0_) do {                                                        \
    if (ACOL) {                                                                 \
        const int m4 = tid & 31, kr = tid >> 5;                                 \
        ar0 = *(const float4*)(A + (size_t)((k0_) + kr)     * lda + m0 + m4*4); \
        ar1 = *(const float4*)(A + (size_t)((k0_) + kr + 8) * lda + m0 + m4*4); \
    } else {                                                                    \
        const int r = tid >> 2, kq = tid & 3;                                   \
        ar0 = *(const float4*)(A + (size_t)(m0 + r)      * lda + (k0_) + kq*4); \
        ar1 = *(const float4*)(A + (size_t)(m0 + r + 64) * lda + (k0_) + kq*4); \
    } } while (0)

#define LOAD_B(k0_) do {                                                        \
    if (TN == 8) {                                                              \
        const int nr = tid >> 1, kq = tid & 1;                                  \
        if (n0 + nr < N) {                                                      \
            const float* bp = B + (size_t)(n0 + nr) * K + (k0_) + kq * 8;       \
            br0 = *(const float4*)(bp);                                         \
            br1 = *(const float4*)(bp + 4);                                     \
        } else { br0 = make_float4(0,0,0,0); br1 = br0; }                       \
    } else {                                                                    \
        const int nr = tid >> 2, kq = tid & 3;                                  \
        br0 = (n0 + nr < N)                                                     \
            ? *(const float4*)(B + (size_t)(n0 + nr) * K + (k0_) + kq*4)        \
            : make_float4(0,0,0,0);                                             \
    } } while (0)

#define STORE_A(st_) do {                                                       \
    if (ACOL) {                                                                 \
        const int m4 = tid & 31, kr = tid >> 5;                                 \
        *(float4*)&As[st_][kr  ][m4*4] = ar0;                                   \
        *(float4*)&As[st_][kr+8][m4*4] = ar1;                                   \
    } else {                                                                    \
        const int r = tid >> 2, kq = tid & 3;                                   \
        As[st_][kq*4+0][r]    = ar0.x; As[st_][kq*4+1][r]    = ar0.y;           \
        As[st_][kq*4+2][r]    = ar0.z; As[st_][kq*4+3][r]    = ar0.w;           \
        As[st_][kq*4+0][r+64] = ar1.x; As[st_][kq*4+1][r+64] = ar1.y;           \
        As[st_][kq*4+2][r+64] = ar1.z; As[st_][kq*4+3][r+64] = ar1.w;           \
    } } while (0)

#define STORE_B(st_) do {                                                       \
    if (TN == 8) {                                                              \
        const int nr = tid >> 1, kq = tid & 1;                                  \
        Bs[st_][kq*8+0][nr] = br0.x; Bs[st_][kq*8+1][nr] = br0.y;               \
        Bs[st_][kq*8+2][nr] = br0.z; Bs[st_][kq*8+3][nr] = br0.w;               \
        Bs[st_][kq*8+4][nr] = br1.x; Bs[st_][kq*8+5][nr] = br1.y;               \
        Bs[st_][kq*8+6][nr] = br1.z; Bs[st_][kq*8+7][nr] = br1.w;               \
    } else {                                                                    \
        const int nr = tid >> 2, kq = tid & 3;                                  \
        Bs[st_][kq*4+0][nr] = br0.x; Bs[st_][kq*4+1][nr] = br0.y;               \
        Bs[st_][kq*4+2][nr] = br0.z; Bs[st_][kq*4+3][nr] = br0.w;               \
    } } while (0)

#define COMPUTE(st_) do {                                                       \
    _Pragma("unroll")                                                           \
    for (int kk = 0; kk < BKT; kk++) {                                          \
        const float* arow = &As[st_][kk][tm * 8];                               \
        ulonglong2 a01 = *(const ulonglong2*)(arow);                            \
        ulonglong2 a23 = *(const ulonglong2*)(arow + 4);                        \
        unsigned long long apk[4] = {a01.x, a01.y, a23.x, a23.y};               \
        float bv[TN];                                                           \
        *(float4*)&bv[0] = *(const float4*)&Bs[st_][kk][tn * TN];               \
        if (TN == 8)                                                            \
            *(float4*)&bv[4] = *(const float4*)&Bs[st_][kk][tn * TN + 4];       \
        _Pragma("unroll")                                                       \
        for (int j = 0; j < TN; j++) {                                          \
            unsigned long long bd = dup2(bv[j]);                                \
            _Pragma("unroll")                                                   \
            for (int p = 0; p < 4; p++) fma2(acc[j][p], apk[p], bd);            \
        }                                                                       \
    } } while (0)

    int k0 = kBase;
    LOAD_A(k0); LOAD_B(k0);
    STORE_A(0); STORE_B(0);
    __syncthreads();
    int st = 0;
    for (int t = 0; t < nT; t++) {
        const bool more = (t + 1 < nT);
        if (more) { LOAD_A(k0 + BKT); LOAD_B(k0 + BKT); }
        COMPUTE(st);
        if (more) {
            STORE_A(st ^ 1); STORE_B(st ^ 1);
            __syncthreads();
            st ^= 1; k0 += BKT;
        }
    }

#undef LOAD_A
#undef LOAD_B
#undef STORE_A
#undef STORE_B
#undef COMPUTE

    // epilogue
    #pragma unroll
    for (int j = 0; j < TN; j++) {
        const int n = n0 + tn * TN + j;
        if (n >= N) continue;
        #pragma unroll
        for (int p = 0; p < 4; p++) {
            const int m = m0 + tm * 8 + 2 * p;
            float2 v = *reinterpret_cast<float2*>(&acc[j][p]);
            if (MODE == 0) {
                float* dst = C + (size_t)blockIdx.z * M * N + (size_t)m * N + n;
                dst[0] = v.x; dst[N] = v.y;
            } else if (MODE == 1) {
                const int half = N >> 1;
                if (n < half)
                    *reinterpret_cast<float2*>(C  + (size_t)n * M + m) = v;
                else
                    *reinterpret_cast<float2*>(C2 + (size_t)(n - half) * M + m) = v;
            } else if (MODE == 2) {
                const float bx = bias[n];
                float a0 = v.x + bx, a1 = v.y + bx;
                a0 = (a0 > 20.f) ? a0 : log1pf(expf(a0));
                a1 = (a1 > 20.f) ? a1 : log1pf(expf(a1));
                *reinterpret_cast<float2*>(C + (size_t)n * M + m) = make_float2(a0, a1);
            } else {
                float* dst = C + (size_t)m * N + n;
                const float* rs = resid + (size_t)m * N + n;
                dst[0] = v.x + rs[0];
                dst[N] = v.y + rs[N];
            }
        }
    }
}

// ---------------------------------------------------------------------------
// split-K reduction for x_proj
// ---------------------------------------------------------------------------
__global__ void __launch_bounds__(256) reduce_k(
    const float* __restrict__ part, float* __restrict__ out, int n)
{
    const int i = blockIdx.x * 256 + threadIdx.x;
    if (i < n) {
        float s = 0.f;
        #pragma unroll
        for (int z = 0; z < SPLITK; z++) s += part[(size_t)z * n + i];
        out[i] = s;
    }
}

// ---------------------------------------------------------------------------
// Depthwise causal conv1d (d_conv=4) + silu. One block per (d, b) row.
// ---------------------------------------------------------------------------
__global__ void __launch_bounds__(256) conv_kernel(
    const float* __restrict__ xt, const float* __restrict__ cw,
    const float* __restrict__ cb, float* __restrict__ xct)
{
    const int row = blockIdx.x;          // 0..4095
    const int d = row >> 1, b = row & 1;
    const size_t base = (size_t)d * NTOK + b * 1024;

    __shared__ float s[1024 + 3];
    const int tid = threadIdx.x;
    const float4 v = reinterpret_cast<const float4*>(xt + base)[tid];
    s[3 + tid*4 + 0] = v.x; s[3 + tid*4 + 1] = v.y;
    s[3 + tid*4 + 2] = v.z; s[3 + tid*4 + 3] = v.w;
    if (tid == 0) { s[0] = 0.f; s[1] = 0.f; s[2] = 0.f; }
    __syncthreads();

    const float w0 = cw[d*4+0], w1 = cw[d*4+1], w2 = cw[d*4+2], w3 = cw[d*4+3];
    const float bs = cb[d];
    float4 o;
    #pragma unroll
    for (int i = 0; i < 4; i++) {
        const int l = tid * 4 + i;
        float r = bs + w0*s[l] + w1*s[l+1] + w2*s[l+2] + w3*s[l+3];
        r = r / (1.f + __expf(-r));     // silu
        ((float*)&o)[i] = r;
    }
    reinterpret_cast<float4*>(xct + base)[tid] = o;
}

// ---------------------------------------------------------------------------
// Selective scan. 16 lanes per (b,d) chain, one lane per state s.
// ---------------------------------------------------------------------------
__global__ void __launch_bounds__(256) scan_kernel(
    const float* __restrict__ xdbl, const float* __restrict__ dtt,
    const float* __restrict__ xct,  const float* __restrict__ zt,
    const float* __restrict__ A_log, const float* __restrict__ Dp,
    float* __restrict__ yt)
{
    const int gt = blockIdx.x * blockDim.x + threadIdx.x;
    const int g = gt >> 4, s = gt & 15;
    const int b = g >> 11, d = g & 2047;

    const float Ac = -expf(A_log[d * DSTATE + s]);
    const float Dd = Dp[d];
    const size_t base = (size_t)d * NTOK + b * 1024;
    const float* __restrict__ dtp = dtt + base;
    const float* __restrict__ xcp = xct + base;
    const float* __restrict__ zp  = zt  + base;
    float*       __restrict__ yp  = yt  + base;
    const float* __restrict__ xd  = xdbl + (size_t)(b * 1024) * XDBL_N;

    float h = 0.f;
    for (int t = 0; t < 1024; t++) {
        const float dt = dtp[t];
        const float xc = xcp[t];
        const float bsv = xd[t * XDBL_N + DTRANK + s];
        const float csv = xd[t * XDBL_N + DTRANK + DSTATE + s];
        const float da = __expf(dt * Ac);
        h = fmaf(da, h, dt * bsv * xc);
        float p = h * csv;
        p += __shfl_xor_sync(0xffffffffu, p, 8, 16);
        p += __shfl_xor_sync(0xffffffffu, p, 4, 16);
        p += __shfl_xor_sync(0xffffffffu, p, 2, 16);
        p += __shfl_xor_sync(0xffffffffu, p, 1, 16);
        if (s == 0) {
            const float zv = zp[t];
            const float gate = zv / (1.f + __expf(-zv));
            yp[t] = (p + xc * Dd) * gate;
        }
    }
}

// ---------------------------------------------------------------------------
// host
// ---------------------------------------------------------------------------
extern "C" void kernel_launch(void* const* d_in, const int* in_sizes, int n_in,
                              void* d_out, int out_size)
{
    const float* x        = (const float*)d_in[0];
    const float* ln_w     = (const float*)d_in[1];
    const float* ln_b     = (const float*)d_in[2];
    const float* in_w     = (const float*)d_in[3];   // (4096, 1024)
    const float* conv_w   = (const float*)d_in[4];   // (2048, 1, 4)
    const float* conv_b   = (const float*)d_in[5];
    const float* xproj_w  = (const float*)d_in[6];   // (96, 2048)
    const float* dtproj_w = (const float*)d_in[7];   // (2048, 64)
    const float* dtproj_b = (const float*)d_in[8];
    const float* A_log    = (const float*)d_in[9];   // (2048, 16)
    const float* Dp       = (const float*)d_in[10];  // (2048,)
    const float* out_w    = (const float*)d_in[11];  // (1024, 2048)
    float* out = (float*)d_out;

    float *h, *xt, *zt, *xct, *dtt, *yt, *xdbl, *xdblp;
    cudaGetSymbolAddress((void**)&h,     g_h);
    cudaGetSymbolAddress((void**)&xt,    g_xt);
    cudaGetSymbolAddress((void**)&zt,    g_zt);
    cudaGetSymbolAddress((void**)&xct,   g_xct);
    cudaGetSymbolAddress((void**)&dtt,   g_dtt);
    cudaGetSymbolAddress((void**)&yt,    g_yt);
    cudaGetSymbolAddress((void**)&xdbl,  g_xdbl);
    cudaGetSymbolAddress((void**)&xdblp, g_xdbl_part);

    // 1. layernorm
    ln_kernel<<<NTOK, 256>>>(x, ln_w, ln_b, h);

    // 2. in_proj: BN=128 tiles
    gemm_k<1, false, 8><<<dim3(4096 / 128, NTOK / BM, 1), 256>>>(
        h, DMODEL, in_w, xt, zt, nullptr, nullptr, NTOK, 2 * DINNER, DMODEL, DMODEL);

    // 3. depthwise conv + silu
    conv_kernel<<<DINNER * 2, 256>>>(xt, conv_w, conv_b, xct);

    // 4. x_proj: split-K=8, BN=64
    gemm_k<0, true, 4><<<dim3(2, NTOK / BM, SPLITK), 256>>>(
        xct, NTOK, xproj_w, xdblp, nullptr, nullptr, nullptr,
        NTOK, XDBL_N, DINNER, DINNER / SPLITK);
    reduce_k<<<(NTOK * XDBL_N + 255) / 256, 256>>>(xdblp, xdbl, NTOK * XDBL_N);

    // 5. dt = softplus(...), BN=128
    gemm_k<2, false, 8><<<dim3(DINNER / 128, NTOK / BM, 1), 256>>>(
        xdbl, XDBL_N, dtproj_w, dtt, nullptr, dtproj_b, nullptr,
        NTOK, DINNER, DTRANK, DTRANK);

    // 6. selective scan
    scan_kernel<<<(2 * DINNER * DSTATE) / 256, 256>>>(
        xdbl, dtt, xct, zt, A_log, Dp, yt);

    // 7. out_proj + residual, BN=64 (256 CTAs > 148 SMs)
    gemm_k<3, true, 4><<<dim3(DMODEL / 64, NTOK / BM, 1), 256>>>(
        yt, NTOK, out_w, out, nullptr, nullptr, x,
        NTOK, DMODEL, DINNER, DINNER);
}

// round 6
// speedup vs baseline: 1.5412x; 1.5216x over previous
#include <cuda_runtime.h>
#include <cuda_bf16.h>
#include <cstdint>

// ---------------------------------------------------------------------------
// MambaBlock on GB300 (compiled as plain sm_103 -> no tcgen05; use mma.sync).
// Big GEMMs (in_proj, out_proj) via warp-level bf16 mma.sync m16n8k16 with
// split-bf16 3-pass (hi/lo) fp32 accumulation. Rest fp32.
// B=2, L=1024, D_MODEL=1024, D_INNER=2048, DT_RANK=64, D_STATE=16, D_CONV=4
// ---------------------------------------------------------------------------

#define NTOK    2048
#define DMODEL  1024
#define DINNER  2048
#define DSTATE  16
#define DTRANK  64
#define XDBL_N  96
#define SPLITK  8

__device__ float g_h   [NTOK * DMODEL];        // LN out, token-major
__device__ float g_xt  [DINNER * NTOK];        // x_in, channel-major
__device__ float g_zt  [DINNER * NTOK];        // z, channel-major
__device__ float g_xct [DINNER * NTOK];        // silu(conv), channel-major
__device__ float g_dtt [DINNER * NTOK];        // softplus(dt), channel-major
__device__ float g_yt  [NTOK * DINNER];        // scan out, TOKEN-major
__device__ float g_xdbl[NTOK * XDBL_N];
__device__ float g_xdbl_part[SPLITK * NTOK * XDBL_N];

// =========================== mma.sync helpers ==============================
__device__ __forceinline__ uint32_t smem_u32(const void* p) {
    uint32_t a;
    asm("{ .reg .u64 t; cvta.to.shared.u64 t, %1; cvt.u32.u64 %0, t; }"
        : "=r"(a) : "l"(p));
    return a;
}

__device__ __forceinline__ void ldm_x4(uint32_t* r, uint32_t addr) {
    asm volatile("ldmatrix.sync.aligned.m8n8.x4.shared.b16 {%0,%1,%2,%3}, [%4];"
        : "=r"(r[0]), "=r"(r[1]), "=r"(r[2]), "=r"(r[3]) : "r"(addr));
}

__device__ __forceinline__ void mma_bf16(float* c, const uint32_t* a,
                                         const uint32_t* b) {
    asm volatile(
        "mma.sync.aligned.m16n8k16.row.col.f32.bf16.bf16.f32 "
        "{%0,%1,%2,%3}, {%4,%5,%6,%7}, {%8,%9}, {%0,%1,%2,%3};"
        : "+f"(c[0]), "+f"(c[1]), "+f"(c[2]), "+f"(c[3])
        : "r"(a[0]), "r"(a[1]), "r"(a[2]), "r"(a[3]), "r"(b[0]), "r"(b[1]));
}

// split-bf16 pair: hi = bf16(x), lo = bf16(x - hi)
__device__ __forceinline__ void cvt2(char* hi, char* lo, int boff,
                                     float e0, float e1) {
    __nv_bfloat162 h2 = __floats2bfloat162_rn(e0, e1);
    const float f0 = __bfloat162float(h2.x), f1 = __bfloat162float(h2.y);
    __nv_bfloat162 l2 = __floats2bfloat162_rn(e0 - f0, e1 - f1);
    *reinterpret_cast<uint32_t*>(hi + boff) = *reinterpret_cast<uint32_t*>(&h2);
    *reinterpret_cast<uint32_t*>(lo + boff) = *reinterpret_cast<uint32_t*>(&l2);
}

// ---------------------------------------------------------------------------
// bf16-split tensor GEMM: D[m][n] = sum_k A[m][k]*B[n][k].
// CTA tile 128x128, Kc=32/stage, double-buffered. 8 warps = 2(m) x 4(n),
// each warp 64x32 via mma.m16n8k16 (4 mfrag x 4 nfrag), 3 passes hi/lo.
// TMODE 0 (in_proj):  store channel-major via smem transpose; n<2048 -> out0
//                     (xt) else out1 (zt).
// TMODE 1 (out_proj): out0[m*1024+n] = D + resid[m*1024+n] (token-major).
// SMEM stage layout (bytes): Ahi[128][40]b16 @0, Alo @10240, Bhi @20480,
// Blo @30720; stage stride 40960; 2 stages = 81920 dynamic bytes.
// ---------------------------------------------------------------------------
#define KC 32
#define STG    40960
#define R_A_LO 10240
#define R_B_HI 20480
#define R_B_LO 30720
#define MM_SMEM 81920

template<int TMODE>
__global__ void __launch_bounds__(256) mm_gemm(
    const float* __restrict__ A, int lda,
    const float* __restrict__ Bw, int ldb, int nchunk,
    float* __restrict__ out0, float* __restrict__ out1,
    const float* __restrict__ resid)
{
    extern __shared__ char smem_dyn[];
    const uint32_t sbase = smem_u32(smem_dyn);
    const int tid  = threadIdx.x;
    const int lane = tid & 31;
    const int w    = tid >> 5;
    const int wm   = w >> 2;            // 0..1  (64-row slab)
    const int wn   = w & 3;             // 0..3  (32-col slab)
    const int n0   = blockIdx.x * 128;
    const int m0   = blockIdx.y * 128;

    // loader indices
    const int lrow = tid >> 1;          // 0..127
    const int lkq  = (tid & 1) * 16;    // 0 or 16

    // ldmatrix lane addressing (within stage, bytes)
    const int a_row  = wm * 64 + (lane & 15);
    const int a_coff = ((lane & 16) ? 16 : 0);
    const int b_row  = wn * 32 + ((lane >> 4) & 1) * 8 + (lane & 7);
    const int b_coff = ((lane & 8) ? 16 : 0);

    float acc[4][4][4];
    #pragma unroll
    for (int i = 0; i < 4; i++)
        #pragma unroll
        for (int j = 0; j < 4; j++)
            #pragma unroll
            for (int p = 0; p < 4; p++) acc[i][j][p] = 0.f;

    float4 va[4], vb[4];

#define LOAD_REGS(c_) do {                                                      \
    const int kc0 = (c_) * KC;                                                  \
    const float4* ag = reinterpret_cast<const float4*>(                         \
        A + (size_t)(m0 + lrow) * lda + kc0 + lkq);                             \
    const float4* bg = reinterpret_cast<const float4*>(                         \
        Bw + (size_t)(n0 + lrow) * ldb + kc0 + lkq);                            \
    _Pragma("unroll") for (int i = 0; i < 4; i++) va[i] = ag[i];                \
    _Pragma("unroll") for (int i = 0; i < 4; i++) vb[i] = bg[i];                \
    } while (0)

#define STORE_STAGE(buf_) do {                                                  \
    char* st = smem_dyn + (buf_) * STG;                                         \
    const int bb = (lrow * 40 + lkq) * 2;                                       \
    _Pragma("unroll") for (int i = 0; i < 4; i++) {                             \
        cvt2(st,           st + R_A_LO, bb + i * 8,     va[i].x, va[i].y);      \
        cvt2(st,           st + R_A_LO, bb + i * 8 + 4, va[i].z, va[i].w);      \
        cvt2(st + R_B_HI,  st + R_B_LO, bb + i * 8,     vb[i].x, vb[i].y);      \
        cvt2(st + R_B_HI,  st + R_B_LO, bb + i * 8 + 4, vb[i].z, vb[i].w);      \
    } } while (0)

#define COMPUTE(buf_) do {                                                      \
    const uint32_t sa = sbase + (buf_) * STG;                                   \
    _Pragma("unroll")                                                           \
    for (int s = 0; s < 2; s++) {                                               \
        uint32_t Ah[4][4], Al[4][4], Bh[2][4], Bl[2][4];                        \
        _Pragma("unroll")                                                       \
        for (int mf = 0; mf < 4; mf++) {                                        \
            const uint32_t ar = sa + (a_row + mf * 16) * 80 + a_coff + s * 32;  \
            ldm_x4(Ah[mf], ar);                                                 \
            ldm_x4(Al[mf], ar + R_A_LO);                                        \
        }                                                                       \
        _Pragma("unroll")                                                       \
        for (int np = 0; np < 2; np++) {                                        \
            const uint32_t br = sa + R_B_HI + (b_row + np * 16) * 80            \
                                + b_coff + s * 32;                              \
            ldm_x4(Bh[np], br);                                                 \
            ldm_x4(Bl[np], br + (R_B_LO - R_B_HI));                             \
        }                                                                       \
        _Pragma("unroll")                                                       \
        for (int mf = 0; mf < 4; mf++)                                          \
            _Pragma("unroll")                                                   \
            for (int nf = 0; nf < 4; nf++) {                                    \
                const uint32_t* bh = &Bh[nf >> 1][(nf & 1) * 2];                \
                const uint32_t* bl = &Bl[nf >> 1][(nf & 1) * 2];                \
                mma_bf16(acc[mf][nf], Ah[mf], bh);                              \
                mma_bf16(acc[mf][nf], Ah[mf], bl);                              \
                mma_bf16(acc[mf][nf], Al[mf], bh);                              \
            }                                                                   \
    } } while (0)

    LOAD_REGS(0);
    STORE_STAGE(0);
    __syncthreads();
    for (int c = 0; c < nchunk; c++) {
        const int buf = c & 1;
        const bool more = (c + 1 < nchunk);
        if (more) LOAD_REGS(c + 1);
        COMPUTE(buf);
        if (more) {
            STORE_STAGE(buf ^ 1);
            __syncthreads();
        }
    }

#undef LOAD_REGS
#undef STORE_STAGE
#undef COMPUTE

    __syncthreads();   // before reusing smem for epilogue

    const int mrow_base = wm * 64;
    const int ncol_base = wn * 32;
    const int rg = lane >> 2;            // row in frag
    const int cp = (lane & 3) * 2;       // col pair in frag

    if (TMODE == 0) {
        // transpose through smem: T[n][m], stride 132 floats
        float* T = reinterpret_cast<float*>(smem_dyn);
        #pragma unroll
        for (int mf = 0; mf < 4; mf++)
            #pragma unroll
            for (int nf = 0; nf < 4; nf++) {
                const int m = mrow_base + mf * 16 + rg;
                const int n = ncol_base + nf * 8 + cp;
                T[(n    ) * 132 + m    ] = acc[mf][nf][0];
                T[(n + 1) * 132 + m    ] = acc[mf][nf][1];
                T[(n    ) * 132 + m + 8] = acc[mf][nf][2];
                T[(n + 1) * 132 + m + 8] = acc[mf][nf][3];
            }
        __syncthreads();
        float* ob; int nc0;
        if (n0 < 2048) { ob = out0; nc0 = n0; }
        else           { ob = out1; nc0 = n0 - 2048; }
        const int n  = tid >> 1;
        const int mh = (tid & 1) * 64;
        const float4* src = reinterpret_cast<const float4*>(&T[n * 132 + mh]);
        float4* dst = reinterpret_cast<float4*>(
            ob + (size_t)(nc0 + n) * NTOK + m0 + mh);
        #pragma unroll
        for (int j = 0; j < 16; j++) dst[j] = src[j];
    } else {
        // token-major + residual, direct float2 stores
        #pragma unroll
        for (int mf = 0; mf < 4; mf++)
            #pragma unroll
            for (int nf = 0; nf < 4; nf++) {
                const int m = m0 + mrow_base + mf * 16 + rg;
                const int n = n0 + ncol_base + nf * 8 + cp;
                {
                    float2 rv = *reinterpret_cast<const float2*>(
                        resid + (size_t)m * DMODEL + n);
                    float2 o = make_float2(acc[mf][nf][0] + rv.x,
                                           acc[mf][nf][1] + rv.y);
                    *reinterpret_cast<float2*>(
                        out0 + (size_t)m * DMODEL + n) = o;
                }
                {
                    float2 rv = *reinterpret_cast<const float2*>(
                        resid + (size_t)(m + 8) * DMODEL + n);
                    float2 o = make_float2(acc[mf][nf][2] + rv.x,
                                           acc[mf][nf][3] + rv.y);
                    *reinterpret_cast<float2*>(
                        out0 + (size_t)(m + 8) * DMODEL + n) = o;
                }
            }
    }
}

// ============================ fp32 kernels =================================
__device__ __forceinline__ unsigned long long dup2(float x) {
    unsigned long long r;
    asm("mov.b64 %0, {%1, %1};" : "=l"(r) : "f"(x));
    return r;
}
__device__ __forceinline__ void fma2(unsigned long long& d,
                                     unsigned long long a,
                                     unsigned long long b) {
    asm("fma.rn.f32x2 %0, %1, %2, %0;" : "+l"(d) : "l"(a), "l"(b));
}

__global__ void __launch_bounds__(256) ln_kernel(
    const float* __restrict__ x, const float* __restrict__ w,
    const float* __restrict__ b, float* __restrict__ out)
{
    const int t = blockIdx.x;
    const float4 v = reinterpret_cast<const float4*>(x + (size_t)t * DMODEL)[threadIdx.x];
    float s  = v.x + v.y + v.z + v.w;
    float sq = v.x*v.x + v.y*v.y + v.z*v.z + v.w*v.w;

    __shared__ float sa[8], sb2[8];
    int lane = threadIdx.x & 31, wrp = threadIdx.x >> 5;
    #pragma unroll
    for (int o = 16; o; o >>= 1) {
        s  += __shfl_down_sync(0xffffffffu, s,  o);
        sq += __shfl_down_sync(0xffffffffu, sq, o);
    }
    if (lane == 0) { sa[wrp] = s; sb2[wrp] = sq; }
    __syncthreads();
    if (wrp == 0) {
        s  = (lane < 8) ? sa[lane] : 0.f;
        sq = (lane < 8) ? sb2[lane] : 0.f;
        #pragma unroll
        for (int o = 4; o; o >>= 1) {
            s  += __shfl_down_sync(0xffffffffu, s,  o);
            sq += __shfl_down_sync(0xffffffffu, sq, o);
        }
        if (lane == 0) { sa[0] = s; sb2[0] = sq; }
    }
    __syncthreads();
    const float mu  = sa[0] * (1.f / DMODEL);
    const float var = sb2[0] * (1.f / DMODEL) - mu * mu;
    const float inv = rsqrtf(var + 1e-5f);

    const float4 wv = reinterpret_cast<const float4*>(w)[threadIdx.x];
    const float4 bv = reinterpret_cast<const float4*>(b)[threadIdx.x];
    float4 o4;
    o4.x = (v.x - mu) * inv * wv.x + bv.x;
    o4.y = (v.y - mu) * inv * wv.y + bv.y;
    o4.z = (v.z - mu) * inv * wv.z + bv.z;
    o4.w = (v.w - mu) * inv * wv.w + bv.w;
    reinterpret_cast<float4*>(out + (size_t)t * DMODEL)[threadIdx.x] = o4;
}

#define BM  128
#define BKT 16
#define APAD 4

template<int MODE, bool ACOL, int TN>
__global__ void __launch_bounds__(256) gemm_k(
    const float* __restrict__ A, int lda, const float* __restrict__ B,
    float* __restrict__ C, float* __restrict__ C2,
    const float* __restrict__ bias, const float* __restrict__ resid,
    int M, int N, int K, int kSplitLen)
{
    constexpr int BN = TN * 16;
    __shared__ __align__(16) float As[2][BKT][BM + APAD];
    __shared__ __align__(16) float Bs[2][BKT][BN];

    const int tid = threadIdx.x;
    const int n0 = blockIdx.x * BN;
    const int m0 = blockIdx.y * BM;
    const int kBase = blockIdx.z * kSplitLen;
    const int nT = kSplitLen / BKT;
    const int tm = tid >> 4, tn = tid & 15;

    unsigned long long acc[TN][4];
    #pragma unroll
    for (int j = 0; j < TN; j++)
        #pragma unroll
        for (int p = 0; p < 4; p++) acc[j][p] = 0ull;

    float4 ar0, ar1, br0, br1;

#define LOAD_A(k0_) do {                                                        \
    if (ACOL) {                                                                 \
        const int m4 = tid & 31, kr = tid >> 5;                                 \
        ar0 = *(const float4*)(A + (size_t)((k0_) + kr)     * lda + m0 + m4*4); \
        ar1 = *(const float4*)(A + (size_t)((k0_) + kr + 8) * lda + m0 + m4*4); \
    } else {                                                                    \
        const int rr = tid >> 2, kq = tid & 3;                                  \
        ar0 = *(const float4*)(A + (size_t)(m0 + rr)      * lda + (k0_) + kq*4);\
        ar1 = *(const float4*)(A + (size_t)(m0 + rr + 64) * lda + (k0_) + kq*4);\
    } } while (0)

#define LOAD_B(k0_) do {                                                        \
    if (TN == 8) {                                                              \
        const int nr = tid >> 1, kq = tid & 1;                                  \
        if (n0 + nr < N) {                                                      \
            const float* bp = B + (size_t)(n0 + nr) * K + (k0_) + kq * 8;       \
            br0 = *(const float4*)(bp);                                         \
            br1 = *(const float4*)(bp + 4);                                     \
        } else { br0 = make_float4(0,0,0,0); br1 = br0; }                       \
    } else {                                                                    \
        const int nr = tid >> 2, kq = tid & 3;                                  \
        br0 = (n0 + nr < N)                                                     \
            ? *(const float4*)(B + (size_t)(n0 + nr) * K + (k0_) + kq*4)        \
            : make_float4(0,0,0,0);                                             \
    } } while (0)

#define STORE_A(st_) do {                                                       \
    if (ACOL) {                                                                 \
        const int m4 = tid & 31, kr = tid >> 5;                                 \
        *(float4*)&As[st_][kr  ][m4*4] = ar0;                                   \
        *(float4*)&As[st_][kr+8][m4*4] = ar1;                                   \
    } else {                                                                    \
        const int rr = tid >> 2, kq = tid & 3;                                  \
        As[st_][kq*4+0][rr]    = ar0.x; As[st_][kq*4+1][rr]    = ar0.y;         \
        As[st_][kq*4+2][rr]    = ar0.z; As[st_][kq*4+3][rr]    = ar0.w;         \
        As[st_][kq*4+0][rr+64] = ar1.x; As[st_][kq*4+1][rr+64] = ar1.y;         \
        As[st_][kq*4+2][rr+64] = ar1.z; As[st_][kq*4+3][rr+64] = ar1.w;         \
    } } while (0)

#define STORE_B(st_) do {                                                       \
    if (TN == 8) {                                                              \
        const int nr = tid >> 1, kq = tid & 1;                                  \
        Bs[st_][kq*8+0][nr] = br0.x; Bs[st_][kq*8+1][nr] = br0.y;               \
        Bs[st_][kq*8+2][nr] = br0.z; Bs[st_][kq*8+3][nr] = br0.w;               \
        Bs[st_][kq*8+4][nr] = br1.x; Bs[st_][kq*8+5][nr] = br1.y;               \
        Bs[st_][kq*8+6][nr] = br1.z; Bs[st_][kq*8+7][nr] = br1.w;               \
    } else {                                                                    \
        const int nr = tid >> 2, kq = tid & 3;                                  \
        Bs[st_][kq*4+0][nr] = br0.x; Bs[st_][kq*4+1][nr] = br0.y;               \
        Bs[st_][kq*4+2][nr] = br0.z; Bs[st_][kq*4+3][nr] = br0.w;               \
    } } while (0)

#define COMPUTE(st_) do {                                                       \
    _Pragma("unroll")                                                           \
    for (int kk = 0; kk < BKT; kk++) {                                          \
        const float* arow = &As[st_][kk][tm * 8];                               \
        ulonglong2 a01 = *(const ulonglong2*)(arow);                            \
        ulonglong2 a23 = *(const ulonglong2*)(arow + 4);                        \
        unsigned long long apk[4] = {a01.x, a01.y, a23.x, a23.y};               \
        float bv[TN];                                                           \
        *(float4*)&bv[0] = *(const float4*)&Bs[st_][kk][tn * TN];               \
        if (TN == 8)                                                            \
            *(float4*)&bv[4] = *(const float4*)&Bs[st_][kk][tn * TN + 4];       \
        _Pragma("unroll")                                                       \
        for (int j = 0; j < TN; j++) {                                          \
            unsigned long long bd = dup2(bv[j]);                                \
            _Pragma("unroll")                                                   \
            for (int p = 0; p < 4; p++) fma2(acc[j][p], apk[p], bd);            \
        }                                                                       \
    } } while (0)

    int k0 = kBase;
    LOAD_A(k0); LOAD_B(k0);
    STORE_A(0); STORE_B(0);
    __syncthreads();
    int st = 0;
    for (int t = 0; t < nT; t++) {
        const bool more = (t + 1 < nT);
        if (more) { LOAD_A(k0 + BKT); LOAD_B(k0 + BKT); }
        COMPUTE(st);
        if (more) {
            STORE_A(st ^ 1); STORE_B(st ^ 1);
            __syncthreads();
            st ^= 1; k0 += BKT;
        }
    }

#undef LOAD_A
#undef LOAD_B
#undef STORE_A
#undef STORE_B
#undef COMPUTE

    #pragma unroll
    for (int j = 0; j < TN; j++) {
        const int n = n0 + tn * TN + j;
        if (n >= N) continue;
        #pragma unroll
        for (int p = 0; p < 4; p++) {
            const int m = m0 + tm * 8 + 2 * p;
            float2 v = *reinterpret_cast<float2*>(&acc[j][p]);
            if (MODE == 0) {
                float* dst = C + (size_t)blockIdx.z * M * N + (size_t)m * N + n;
                dst[0] = v.x; dst[N] = v.y;
            } else if (MODE == 2) {
                const float bx = bias[n];
                float a0 = v.x + bx, a1 = v.y + bx;
                a0 = (a0 > 20.f) ? a0 : log1pf(expf(a0));
                a1 = (a1 > 20.f) ? a1 : log1pf(expf(a1));
                *reinterpret_cast<float2*>(C + (size_t)n * M + m) = make_float2(a0, a1);
            }
        }
    }
}

__global__ void __launch_bounds__(256) reduce_k(
    const float* __restrict__ part, float* __restrict__ out, int n)
{
    const int i = blockIdx.x * 256 + threadIdx.x;
    if (i < n) {
        float s = 0.f;
        #pragma unroll
        for (int z = 0; z < SPLITK; z++) s += part[(size_t)z * n + i];
        out[i] = s;
    }
}

__global__ void __launch_bounds__(256) conv_kernel(
    const float* __restrict__ xt, const float* __restrict__ cw,
    const float* __restrict__ cb, float* __restrict__ xct)
{
    const int row = blockIdx.x;
    const int d = row >> 1, b = row & 1;
    const size_t base = (size_t)d * NTOK + b * 1024;

    __shared__ float s[1024 + 3];
    const int tid = threadIdx.x;
    const float4 v = reinterpret_cast<const float4*>(xt + base)[tid];
    s[3 + tid*4 + 0] = v.x; s[3 + tid*4 + 1] = v.y;
    s[3 + tid*4 + 2] = v.z; s[3 + tid*4 + 3] = v.w;
    if (tid == 0) { s[0] = 0.f; s[1] = 0.f; s[2] = 0.f; }
    __syncthreads();

    const float w0 = cw[d*4+0], w1 = cw[d*4+1], w2 = cw[d*4+2], w3 = cw[d*4+3];
    const float bs = cb[d];
    float4 o;
    #pragma unroll
    for (int i = 0; i < 4; i++) {
        const int l = tid * 4 + i;
        float r = bs + w0*s[l] + w1*s[l+1] + w2*s[l+2] + w3*s[l+3];
        r = r / (1.f + __expf(-r));
        ((float*)&o)[i] = r;
    }
    reinterpret_cast<float4*>(xct + base)[tid] = o;
}

__global__ void __launch_bounds__(256) scan_kernel(
    const float* __restrict__ xdbl, const float* __restrict__ dtt,
    const float* __restrict__ xct,  const float* __restrict__ zt,
    const float* __restrict__ A_log, const float* __restrict__ Dp,
    float* __restrict__ yt)
{
    const int gt = blockIdx.x * blockDim.x + threadIdx.x;
    const int g = gt >> 4, s = gt & 15;
    const int b = g >> 11, d = g & 2047;

    const float Ac = -expf(A_log[d * DSTATE + s]);
    const float Dd = Dp[d];
    const size_t base = (size_t)d * NTOK + b * 1024;
    const float* __restrict__ dtp = dtt + base;
    const float* __restrict__ xcp = xct + base;
    const float* __restrict__ zp  = zt  + base;
    float*       __restrict__ yp  = yt + (size_t)b * 1024 * DINNER + d;  // token-major
    const float* __restrict__ xd  = xdbl + (size_t)(b * 1024) * XDBL_N;

    float h = 0.f;
    for (int t = 0; t < 1024; t++) {
        const float dt = dtp[t];
        const float xc = xcp[t];
        const float bsv = xd[t * XDBL_N + DTRANK + s];
        const float csv = xd[t * XDBL_N + DTRANK + DSTATE + s];
        const float da = __expf(dt * Ac);
        h = fmaf(da, h, dt * bsv * xc);
        float p = h * csv;
        p += __shfl_xor_sync(0xffffffffu, p, 8, 16);
        p += __shfl_xor_sync(0xffffffffu, p, 4, 16);
        p += __shfl_xor_sync(0xffffffffu, p, 2, 16);
        p += __shfl_xor_sync(0xffffffffu, p, 1, 16);
        if (s == 0) {
            const float zv = zp[t];
            const float gate = zv / (1.f + __expf(-zv));
            yp[(size_t)t * DINNER] = (p + xc * Dd) * gate;
        }
    }
}

// ---------------------------------------------------------------------------
// host
// ---------------------------------------------------------------------------
extern "C" void kernel_launch(void* const* d_in, const int* in_sizes, int n_in,
                              void* d_out, int out_size)
{
    const float* x        = (const float*)d_in[0];
    const float* ln_w     = (const float*)d_in[1];
    const float* ln_b     = (const float*)d_in[2];
    const float* in_w     = (const float*)d_in[3];
    const float* conv_w   = (const float*)d_in[4];
    const float* conv_b   = (const float*)d_in[5];
    const float* xproj_w  = (const float*)d_in[6];
    const float* dtproj_w = (const float*)d_in[7];
    const float* dtproj_b = (const float*)d_in[8];
    const float* A_log    = (const float*)d_in[9];
    const float* Dp       = (const float*)d_in[10];
    const float* out_w    = (const float*)d_in[11];
    float* out = (float*)d_out;

    float *h, *xt, *zt, *xct, *dtt, *yt, *xdbl, *xdblp;
    cudaGetSymbolAddress((void**)&h,     g_h);
    cudaGetSymbolAddress((void**)&xt,    g_xt);
    cudaGetSymbolAddress((void**)&zt,    g_zt);
    cudaGetSymbolAddress((void**)&xct,   g_xct);
    cudaGetSymbolAddress((void**)&dtt,   g_dtt);
    cudaGetSymbolAddress((void**)&yt,    g_yt);
    cudaGetSymbolAddress((void**)&xdbl,  g_xdbl);
    cudaGetSymbolAddress((void**)&xdblp, g_xdbl_part);

    cudaFuncSetAttribute(mm_gemm<0>, cudaFuncAttributeMaxDynamicSharedMemorySize,
                         MM_SMEM);
    cudaFuncSetAttribute(mm_gemm<1>, cudaFuncAttributeMaxDynamicSharedMemorySize,
                         MM_SMEM);

    // 1. layernorm
    ln_kernel<<<NTOK, 256>>>(x, ln_w, ln_b, h);

    // 2. in_proj (mma.sync bf16-split): M=2048, N=4096, K=1024 -> xt/zt ch-major
    mm_gemm<0><<<dim3(4096 / 128, NTOK / 128), 256, MM_SMEM>>>(
        h, DMODEL, in_w, DMODEL, DMODEL / KC, xt, zt, nullptr);

    // 3. depthwise conv + silu
    conv_kernel<<<DINNER * 2, 256>>>(xt, conv_w, conv_b, xct);

    // 4. x_proj (fp32 split-K)
    gemm_k<0, true, 4><<<dim3(2, NTOK / BM, SPLITK), 256>>>(
        xct, NTOK, xproj_w, xdblp, nullptr, nullptr, nullptr,
        NTOK, XDBL_N, DINNER, DINNER / SPLITK);
    reduce_k<<<(NTOK * XDBL_N + 255) / 256, 256>>>(xdblp, xdbl, NTOK * XDBL_N);

    // 5. dt = softplus(...) (fp32)
    gemm_k<2, false, 8><<<dim3(DINNER / 128, NTOK / BM, 1), 256>>>(
        xdbl, XDBL_N, dtproj_w, dtt, nullptr, dtproj_b, nullptr,
        NTOK, DINNER, DTRANK, DTRANK);

    // 6. selective scan -> yt token-major
    scan_kernel<<<(2 * DINNER * DSTATE) / 256, 256>>>(
        xdbl, dtt, xct, zt, A_log, Dp, yt);

    // 7. out_proj + residual (mma.sync): M=2048, N=1024, K=2048, token-major out
    mm_gemm<1><<<dim3(DMODEL / 128, NTOK / 128), 256, MM_SMEM>>>(
        yt, DINNER, out_w, DINNER, DINNER / KC, out, nullptr, x);
}